// round 4
// baseline (speedup 1.0000x reference)
#include <cuda_runtime.h>
#include <cuda_bf16.h>
#include <math.h>
#include <float.h>
#include <stdint.h>

namespace {
constexpr int Nn = 4096, Cc = 512, Hh = 128, Tt = 64, Dd = 20, Kt = 10, G = 384;

constexpr size_t SZ_GX = (size_t)Tt * Nn * G;
constexpr size_t SZ_OUT0 = (size_t)Tt * Nn * Hh;
constexpr size_t SZ_NH = (size_t)Nn * Hh;
constexpr size_t SZ_WT = (size_t)Hh * G;
constexpr size_t SZ_CH = (size_t)Cc * Hh;
constexpr size_t SZ_NC = (size_t)Nn * Cc;
constexpr size_t SZ_BIG = (size_t)Nn * Nn;

constexpr size_t OFF_GX = 0;
constexpr size_t OFF_OUT0 = OFF_GX + SZ_GX;
constexpr size_t OFF_HA = OFF_OUT0 + SZ_OUT0;
constexpr size_t OFF_HB = OFF_HA + SZ_NH;
constexpr size_t OFF_WT0 = OFF_HB + SZ_NH;
constexpr size_t OFF_WT1 = OFF_WT0 + SZ_WT;
constexpr size_t OFF_WIH1T = OFF_WT1 + SZ_WT;
constexpr size_t OFF_DEN = OFF_WIH1T + SZ_WT;
constexpr size_t OFF_HIDDEN = OFF_DEN + Cc;
constexpr size_t OFF_V1 = OFF_HIDDEN + SZ_CH;
constexpr size_t OFF_LOGITS = OFF_V1 + Cc;
constexpr size_t OFF_CMAX = OFF_LOGITS + SZ_NC;
constexpr size_t OFF_CSUM = OFF_CMAX + Cc;
constexpr size_t OFF_HIDDEN2 = OFF_CSUM + Cc;
constexpr size_t OFF_NY = OFF_HIDDEN2 + SZ_CH;
constexpr size_t OFF_NX = OFF_NY + Cc;
constexpr size_t OFF_C2S = OFF_NX + Nn;
constexpr size_t OFF_PRAW = OFF_C2S + SZ_NC;
constexpr size_t OFF_PSH = OFF_PRAW + SZ_NH;
constexpr size_t OFF_PBACK = OFF_PSH + SZ_NH;
constexpr size_t OFF_OUTPS = OFF_PBACK + SZ_NH;
constexpr size_t OFF_HSH = OFF_OUTPS + SZ_NH;
constexpr size_t OFF_NHS = OFF_HSH + SZ_NH;
constexpr size_t OFF_DIAG = OFF_NHS + Nn;
constexpr size_t OFF_BIG = OFF_DIAG + Nn;
constexpr size_t OFF_TOPV = OFF_BIG + SZ_BIG;
constexpr size_t OFF_HH = OFF_TOPV + (size_t)Nn * Kt;
constexpr size_t OFF_COLSUM = OFF_HH + SZ_NH;
constexpr size_t OFF_V2 = OFF_COLSUM + Nn;
constexpr size_t OFF_NHH = OFF_V2 + Nn;
constexpr size_t OFF_HSIRAW = OFF_NHH + Nn;
constexpr size_t OFF_HSI = OFF_HSIRAW + SZ_NH;
constexpr size_t OFF_HBACK = OFF_HSI + SZ_NH;
constexpr size_t OFF_OUTHS = OFF_HBACK + SZ_NH;
constexpr size_t OFF_OUTIN = OFF_OUTHS + SZ_NH;
constexpr size_t OFF_XT = OFF_OUTIN + SZ_NH;
constexpr size_t OFF_WIH0T = OFF_XT + (size_t)Tt * Nn * Dd;
constexpr size_t TOTAL = OFF_WIH0T + (size_t)Dd * G;

constexpr int SMEM_L = (128 * G + 32 * Hh + 32 * Dd) * 4;  // 215552 bytes
}  // namespace

__device__ float g_buf[TOTAL];
__device__ int g_topi[Nn * Kt];

__device__ __forceinline__ float fsig(float x) {
    return __fdividef(1.f, 1.f + __expf(-x));
}
__device__ __forceinline__ float ftanh(float x) {
    float y;
    asm("tanh.approx.f32 %0, %1;" : "=f"(y) : "f"(x));
    return y;
}

// ---- packed f32x2 helpers -------------------------------------------------
typedef unsigned long long u64;
#define FMA2(acc, a, b) \
    asm("fma.rn.f32x2 %0, %1, %2, %0;" : "+l"(acc) : "l"(a), "l"(b))

__device__ __forceinline__ u64 pk2(float lo, float hi) {
    u64 r;
    asm("mov.b64 %0, {%1, %2};" : "=l"(r)
        : "r"(__float_as_uint(lo)), "r"(__float_as_uint(hi)));
    return r;
}
__device__ __forceinline__ u64 bc2(float v) { return pk2(v, v); }
__device__ __forceinline__ float2 up2(u64 p) {
    unsigned int lo, hi;
    asm("mov.b64 {%0, %1}, %2;" : "=r"(lo), "=r"(hi) : "l"(p));
    return make_float2(__uint_as_float(lo), __uint_as_float(hi));
}

// ---------------------------------------------------------------------------
__global__ void k_zero(float* p, int n) {
    int i = blockIdx.x * blockDim.x + threadIdx.x;
    if (i < n) p[i] = 0.f;
}

// transpose [G,H] -> [H,G] for whh0, whh1, wih1
__global__ void k_prep(const float* __restrict__ w0, const float* __restrict__ w1,
                       const float* __restrict__ w2, float* __restrict__ t0,
                       float* __restrict__ t1, float* __restrict__ t2) {
    int i = blockIdx.x * blockDim.x + threadIdx.x;
    if (i >= G * Hh) return;
    int r = i / Hh, c = i % Hh;
    t0[c * G + r] = w0[i];
    t1[c * G + r] = w1[i];
    t2[c * G + r] = w2[i];
}

// wih0 [G,D] -> [D,G]
__global__ void k_prep0(const float* __restrict__ w, float* __restrict__ t) {
    int i = blockIdx.x * blockDim.x + threadIdx.x;
    if (i >= G * Dd) return;
    int r = i / Dd, c = i % Dd;
    t[c * G + r] = w[i];
}

// x [N, D*T] -> xt [T, N, D]
__global__ void k_xt(const float* __restrict__ x, float* __restrict__ xt) {
    int i = blockIdx.x * blockDim.x + threadIdx.x;
    if (i >= Nn * Dd * Tt) return;
    int t = i % Tt;
    int d = (i / Tt) % Dd;
    int n = i / (Tt * Dd);
    xt[((size_t)t * Nn + n) * Dd + d] = x[i];
}

// ---------------------------------------------------------------------------
// Persistent GRU layer, FFMA2 packed (rows paired). grid=128, 512 threads.
// hs2[mp][k] = (h[2mp,k], h[2mp+1,k]) float2 -> one LDS.128 feeds 2 k-steps
// of 2 rows, directly usable as packed operands (no pack instr on h).
// ---------------------------------------------------------------------------
template <bool L0>
__global__ __launch_bounds__(512, 1) void k_gru_layer(
    const float* __restrict__ xin,  // L0: xt [T,N,D]; L1: gx [T,N,G]
    const float* __restrict__ wih0t, const float* __restrict__ bih0,
    const float* __restrict__ wt, const float* __restrict__ bhh,
    float* __restrict__ out0, float* __restrict__ xh) {
    extern __shared__ float sm[];
    float* ws = sm;                               // [128][384]  w[k][gatecol]
    float2* hs2 = (float2*)(sm + 128 * G);        // [16][128] row pairs
    float2* xsp = (float2*)(sm + 128 * G + 32 * Hh);  // [16][20] row pairs
    int tid = threadIdx.x;
    int j = tid & 127, rg = tid >> 7;  // rg 0..3
    int n0 = blockIdx.x * 32;
    int r0 = rg * 8;        // first row of this thread group
    int mp0 = rg * 4;       // first row-pair

    {
        const float4* s = (const float4*)wt;
        float4* d = (float4*)ws;
        for (int e = tid; e < 128 * G / 4; e += 512) d[e] = s[e];
    }
    for (int e = tid; e < 16 * Hh; e += 512) hs2[e] = make_float2(0.f, 0.f);

    float br = bhh[j], bz = bhh[j + 128], bn = bhh[j + 256];
    u64 BN2 = bc2(bn);
    u64 BR2 = 0, BZ2 = 0, BIN2 = 0;
    if (L0) {
        BR2 = bc2(br + bih0[j]);
        BZ2 = bc2(bz + bih0[j + 128]);
        BIN2 = bc2(bih0[j + 256]);
    }

    for (int t = 0; t < Tt; t++) {
        if (L0) {
            const float* src = xin + ((size_t)t * Nn + n0) * Dd;
            for (int e = tid; e < 32 * Dd; e += 512) {
                int m = e / Dd, d = e % Dd;
                ((float*)&xsp[(m >> 1) * Dd + d])[m & 1] = src[e];
            }
        }
        __syncthreads();

        u64 AR[4], AZ[4], AXN[4], AHN[4];
        if (L0) {
#pragma unroll
            for (int mp = 0; mp < 4; mp++) {
                AR[mp] = BR2; AZ[mp] = BZ2; AXN[mp] = BIN2; AHN[mp] = BN2;
            }
#pragma unroll 4
            for (int d = 0; d < Dd; d++) {
                u64 WR = bc2(wih0t[d * G + j]);
                u64 WZ = bc2(wih0t[d * G + j + 128]);
                u64 WN = bc2(wih0t[d * G + j + 256]);
#pragma unroll
                for (int mp = 0; mp < 4; mp++) {
                    u64 xp = *(const u64*)&xsp[(mp0 + mp) * Dd + d];
                    FMA2(AR[mp], xp, WR);
                    FMA2(AZ[mp], xp, WZ);
                    FMA2(AXN[mp], xp, WN);
                }
            }
        } else {
            const float* gp = xin + ((size_t)t * Nn + n0) * G;
#pragma unroll
            for (int mp = 0; mp < 4; mp++) {
                int ra = (r0 + 2 * mp) * G, rb = (r0 + 2 * mp + 1) * G;
                AR[mp] = pk2(gp[ra + j] + br, gp[rb + j] + br);
                AZ[mp] = pk2(gp[ra + j + 128] + bz, gp[rb + j + 128] + bz);
                AXN[mp] = pk2(gp[ra + j + 256], gp[rb + j + 256]);
                AHN[mp] = BN2;
            }
        }

        // recurrent GEMM: packed over row pairs, 2 k per iter
        for (int k = 0; k < Hh; k += 2) {
            u64 WR0 = bc2(ws[k * G + j]);
            u64 WZ0 = bc2(ws[k * G + j + 128]);
            u64 WN0 = bc2(ws[k * G + j + 256]);
            u64 WR1 = bc2(ws[(k + 1) * G + j]);
            u64 WZ1 = bc2(ws[(k + 1) * G + j + 128]);
            u64 WN1 = bc2(ws[(k + 1) * G + j + 256]);
#pragma unroll
            for (int mp = 0; mp < 4; mp++) {
                ulonglong2 hp = *(const ulonglong2*)&hs2[(mp0 + mp) * Hh + k];
                FMA2(AR[mp], hp.x, WR0);
                FMA2(AZ[mp], hp.x, WZ0);
                FMA2(AHN[mp], hp.x, WN0);
                FMA2(AR[mp], hp.y, WR1);
                FMA2(AZ[mp], hp.y, WZ1);
                FMA2(AHN[mp], hp.y, WN1);
            }
        }

        float2 hnew[4];
#pragma unroll
        for (int mp = 0; mp < 4; mp++) {
            float2 ar = up2(AR[mp]), az = up2(AZ[mp]);
            float2 axn = up2(AXN[mp]), ahn = up2(AHN[mp]);
            float2 hold = hs2[(mp0 + mp) * Hh + j];
            float r0f = fsig(ar.x), z0f = fsig(az.x);
            float n0f = ftanh(axn.x + r0f * ahn.x);
            float r1f = fsig(ar.y), z1f = fsig(az.y);
            float n1f = ftanh(axn.y + r1f * ahn.y);
            hnew[mp].x = (1.f - z0f) * n0f + z0f * hold.x;
            hnew[mp].y = (1.f - z1f) * n1f + z1f * hold.y;
        }
        __syncthreads();
#pragma unroll
        for (int mp = 0; mp < 4; mp++) {
            hs2[(mp0 + mp) * Hh + j] = hnew[mp];
            int na = n0 + r0 + 2 * mp;
            if (L0) {
                out0[((size_t)t * Nn + na) * Hh + j] = hnew[mp].x;
                out0[((size_t)t * Nn + na + 1) * Hh + j] = hnew[mp].y;
            } else if (t == Tt - 1) {
                xh[(size_t)na * Hh + j] = hnew[mp].x;
                xh[(size_t)(na + 1) * Hh + j] = hnew[mp].y;
            }
        }
    }
}

// ---------------------------------------------------------------------------
// gx1 = out0 @ wih1T + bih1, FFMA2 packed (row pairs). TM=32, 256 threads.
// ---------------------------------------------------------------------------
__global__ __launch_bounds__(256, 2) void k_gemm_g3(
    const float* __restrict__ A, const float* __restrict__ WT,
    const float* __restrict__ bias, float* __restrict__ Cout) {
    __shared__ float2 As2[16 * Hh];  // row pairs
    int tid = threadIdx.x;
    int j = tid & 127, rg = tid >> 7;  // rg 0..1
    int m0 = blockIdx.x * 32;
    {
        const float* src = A + (size_t)m0 * Hh;
        for (int e = tid; e < 32 * Hh; e += 256) {
            int m = e >> 7, k = e & 127;
            ((float*)&As2[(m >> 1) * Hh + k])[m & 1] = src[e];
        }
    }
    __syncthreads();
    int mp0 = rg * 8;
    u64 AR[8], AZ[8], AN[8];
#pragma unroll
    for (int mp = 0; mp < 8; mp++) { AR[mp] = 0; AZ[mp] = 0; AN[mp] = 0; }
    for (int k = 0; k < Hh; k += 2) {
        u64 WR0 = bc2(WT[k * G + j]);
        u64 WZ0 = bc2(WT[k * G + j + 128]);
        u64 WN0 = bc2(WT[k * G + j + 256]);
        u64 WR1 = bc2(WT[(k + 1) * G + j]);
        u64 WZ1 = bc2(WT[(k + 1) * G + j + 128]);
        u64 WN1 = bc2(WT[(k + 1) * G + j + 256]);
#pragma unroll
        for (int mp = 0; mp < 8; mp++) {
            ulonglong2 hp = *(const ulonglong2*)&As2[(mp0 + mp) * Hh + k];
            FMA2(AR[mp], hp.x, WR0);
            FMA2(AZ[mp], hp.x, WZ0);
            FMA2(AN[mp], hp.x, WN0);
            FMA2(AR[mp], hp.y, WR1);
            FMA2(AZ[mp], hp.y, WZ1);
            FMA2(AN[mp], hp.y, WN1);
        }
    }
    float br = bias[j], bz = bias[j + 128], bn = bias[j + 256];
#pragma unroll
    for (int mp = 0; mp < 8; mp++) {
        float2 ar = up2(AR[mp]), az = up2(AZ[mp]), an = up2(AN[mp]);
        size_t ba = (size_t)(m0 + 2 * (mp0 + mp)) * G;
        size_t bb = ba + G;
        Cout[ba + j] = ar.x + br;
        Cout[ba + j + 128] = az.x + bz;
        Cout[ba + j + 256] = an.x + bn;
        Cout[bb + j] = ar.y + br;
        Cout[bb + j + 128] = az.y + bz;
        Cout[bb + j + 256] = an.y + bn;
    }
}

// den[c] = sum_n cm[n,c]*mv[n]
__global__ void k_den(const float* __restrict__ cm, const float* __restrict__ mv,
                      float* __restrict__ den) {
    int c = blockIdx.x * 128 + threadIdx.x;
    int nb = blockIdx.y;
    float s = 0.f;
    for (int n = nb * 512; n < (nb + 1) * 512; n++) s += cm[(size_t)n * Cc + c] * mv[n];
    atomicAdd(&den[c], s);
}

// Weighted aggregation into [C,H]: mode 0 -> hidden (+v1), mode 1 -> hidden2 (+norm)
__global__ void k_cagg(const float* __restrict__ cm, const float* __restrict__ mv,
                       const float* __restrict__ den, const float* __restrict__ logits,
                       const float* __restrict__ cmax, const float* __restrict__ csum,
                       const float* __restrict__ xh, float* __restrict__ outp,
                       float* __restrict__ aux, int mode) {
    __shared__ float xs[64][Hh];
    __shared__ float cs[64][8];
    __shared__ float red[256];
    int c0 = blockIdx.x * 8;
    int tid = threadIdx.x;
    int h = tid & 127, g = tid >> 7;
    float acc[4] = {0.f, 0.f, 0.f, 0.f};
    for (int nb = 0; nb < Nn; nb += 64) {
        for (int e = tid; e < 64 * Hh; e += 256)
            xs[e >> 7][e & 127] = xh[(size_t)(nb + (e >> 7)) * Hh + (e & 127)];
        for (int e = tid; e < 64 * 8; e += 256) {
            int nn = e >> 3, ci = e & 7;
            int n = nb + nn, c = c0 + ci;
            float coef;
            if (mode == 0) {
                float cv = cm[(size_t)n * Cc + c];
                coef = cv * mv[n] / (den[c] * cv + 1.f);
            } else {
                coef = __expf(logits[(size_t)n * Cc + c] - cmax[c]) / csum[c];
            }
            cs[nn][ci] = coef;
        }
        __syncthreads();
#pragma unroll 4
        for (int nn = 0; nn < 64; nn++) {
            float xv = xs[nn][h];
#pragma unroll
            for (int u = 0; u < 4; u++) acc[u] += cs[nn][g + 2 * u] * xv;
        }
        __syncthreads();
    }
#pragma unroll
    for (int u = 0; u < 4; u++) outp[(size_t)(c0 + g + 2 * u) * Hh + h] = acc[u];
    for (int u = 0; u < 4; u++) {
        red[tid] = (mode == 0) ? acc[u] : acc[u] * acc[u];
        __syncthreads();
        for (int st = 64; st > 0; st >>= 1) {
            if (h < st) red[tid] += red[tid + st];
            __syncthreads();
        }
        if (h == 0) {
            int c = c0 + g + 2 * u;
            aux[c] = (mode == 0) ? ((red[tid] != 0.f) ? 1.f : 0.f) : sqrtf(red[tid]);
        }
        __syncthreads();
    }
}

// Out = A [- B]; nrm = ||row||; diag = ss/max(ss,1e-12)
__global__ void k_subnorm(const float* __restrict__ A, const float* __restrict__ B,
                          float* __restrict__ Out, float* __restrict__ nrm,
                          float* __restrict__ diag) {
    __shared__ float red[128];
    int n = blockIdx.x;
    int tid = threadIdx.x;
    float v = A[(size_t)n * Hh + tid];
    if (B) v -= B[(size_t)n * Hh + tid];
    Out[(size_t)n * Hh + tid] = v;
    red[tid] = v * v;
    __syncthreads();
    for (int st = 64; st > 0; st >>= 1) {
        if (tid < st) red[tid] += red[tid + st];
        __syncthreads();
    }
    if (tid == 0) {
        float ss = red[0];
        nrm[n] = sqrtf(ss);
        if (diag) diag[n] = ss / fmaxf(ss, 1e-12f);
    }
}

// NT GEMM, K=128; flags: 1=cosine-normalize, 2=zero diag
__global__ void k_gemm_nt(const float* __restrict__ A, const float* __restrict__ B,
                          const float* __restrict__ nx, const float* __restrict__ ny,
                          float* __restrict__ Cmat, int Ndim, int flags) {
    __shared__ float As[64][33];
    __shared__ float Bs[64][33];
    int m0 = blockIdx.y * 64, n0 = blockIdx.x * 64;
    int tid = threadIdx.x;
    int ty = tid / 16, tx = tid % 16;
    float acc[4][4];
#pragma unroll
    for (int i = 0; i < 4; i++)
#pragma unroll
        for (int jj = 0; jj < 4; jj++) acc[i][jj] = 0.f;
    for (int kc = 0; kc < Hh; kc += 32) {
        for (int e = tid; e < 64 * 32; e += 256) {
            int r = e / 32, c = e % 32;
            As[r][c] = A[(size_t)(m0 + r) * Hh + kc + c];
            Bs[r][c] = B[(size_t)(n0 + r) * Hh + kc + c];
        }
        __syncthreads();
#pragma unroll 8
        for (int kk = 0; kk < 32; kk++) {
            float a[4], b[4];
#pragma unroll
            for (int i = 0; i < 4; i++) a[i] = As[ty * 4 + i][kk];
#pragma unroll
            for (int jj = 0; jj < 4; jj++) b[jj] = Bs[tx * 4 + jj][kk];
#pragma unroll
            for (int i = 0; i < 4; i++)
#pragma unroll
                for (int jj = 0; jj < 4; jj++) acc[i][jj] += a[i] * b[jj];
        }
        __syncthreads();
    }
#pragma unroll
    for (int i = 0; i < 4; i++) {
        int gm = m0 + ty * 4 + i;
#pragma unroll
        for (int jj = 0; jj < 4; jj++) {
            int gn = n0 + tx * 4 + jj;
            float v = acc[i][jj];
            if (flags & 1) v = v / fmaxf(nx[gm] * ny[gn], 1e-12f);
            if ((flags & 2) && gm == gn) v = 0.f;
            Cmat[(size_t)gm * Ndim + gn] = v;
        }
    }
}

// column reduce over logits [N,C]
__global__ void k_colreduce(const float* __restrict__ logits, float* __restrict__ cmax,
                            float* __restrict__ csum) {
    __shared__ float col[Nn];
    __shared__ float red[256];
    int c = blockIdx.x;
    int tid = threadIdx.x;
    for (int n = tid; n < Nn; n += 256) col[n] = logits[(size_t)n * Cc + c];
    __syncthreads();
    float m = -FLT_MAX;
    for (int n = tid; n < Nn; n += 256) m = fmaxf(m, col[n]);
    red[tid] = m;
    __syncthreads();
    for (int st = 128; st > 0; st >>= 1) {
        if (tid < st) red[tid] = fmaxf(red[tid], red[tid + st]);
        __syncthreads();
    }
    float mx = red[0];
    __syncthreads();
    float s = 0.f;
    for (int n = tid; n < Nn; n += 256) s += __expf(col[n] - mx);
    red[tid] = s;
    __syncthreads();
    for (int st = 128; st > 0; st >>= 1) {
        if (tid < st) red[tid] += red[tid + st];
        __syncthreads();
    }
    if (tid == 0) { cmax[c] = mx; csum[c] = red[0]; }
}

// row softmax with validity mask, in place
__global__ void k_rowsoftmax(float* __restrict__ mat, const float* __restrict__ v, int W) {
    __shared__ float buf[Nn];
    __shared__ float red[256];
    int row = blockIdx.x;
    int tid = threadIdx.x;
    float* r = mat + (size_t)row * W;
    for (int i = tid; i < W; i += 256) buf[i] = (v[i] != 0.f) ? r[i] : -1e9f;
    __syncthreads();
    float m = -FLT_MAX;
    for (int i = tid; i < W; i += 256) m = fmaxf(m, buf[i]);
    red[tid] = m;
    __syncthreads();
    for (int st = 128; st > 0; st >>= 1) {
        if (tid < st) red[tid] = fmaxf(red[tid], red[tid + st]);
        __syncthreads();
    }
    float mx = red[0];
    __syncthreads();
    float s = 0.f;
    for (int i = tid; i < W; i += 256) s += __expf(buf[i] - mx);
    red[tid] = s;
    __syncthreads();
    for (int st = 128; st > 0; st >>= 1) {
        if (tid < st) red[tid] += red[tid + st];
        __syncthreads();
    }
    float inv = 1.f / red[0];
    for (int i = tid; i < W; i += 256)
        r[i] = (v[i] != 0.f) ? __expf(buf[i] - mx) * inv : 0.f;
}

// NN GEMM: C[M,128] = A[M,K] @ B[K,128]
__global__ void k_gemm_nn(const float* __restrict__ A, const float* __restrict__ B,
                          float* __restrict__ Cout, int K) {
    __shared__ float As[16][65];
    int m0 = blockIdx.x * 16;
    int tid = threadIdx.x;
    int j = tid & 127, half = tid >> 7;
    float acc[8];
#pragma unroll
    for (int r = 0; r < 8; r++) acc[r] = 0.f;
    for (int ck = 0; ck < K; ck += 64) {
        for (int e = tid; e < 16 * 64; e += 256)
            As[e / 64][e % 64] = A[(size_t)(m0 + e / 64) * K + ck + (e % 64)];
        __syncthreads();
#pragma unroll 4
        for (int kk = 0; kk < 64; kk++) {
            float b = B[(size_t)(ck + kk) * Hh + j];
#pragma unroll
            for (int r = 0; r < 8; r++) acc[r] += As[half * 8 + r][kk] * b;
        }
        __syncthreads();
    }
#pragma unroll
    for (int r = 0; r < 8; r++) Cout[(size_t)(m0 + half * 8 + r) * Hh + j] = acc[r];
}

// Dense H->H: C = (A0 [-A1] [-A2]) @ W^T + bias, optional leaky relu
__global__ void k_dense(const float* __restrict__ A0, const float* __restrict__ A1,
                        const float* __restrict__ A2, const float* __restrict__ W,
                        const float* __restrict__ bias, float* __restrict__ Cout, int leaky) {
    __shared__ float As[16][Hh];
    int m0 = blockIdx.x * 16;
    int tid = threadIdx.x;
    for (int e = tid; e < 16 * Hh; e += 128) {
        int m = e >> 7, h = e & 127;
        size_t idx = (size_t)(m0 + m) * Hh + h;
        float v = A0[idx];
        if (A1) v -= A1[idx];
        if (A2) v -= A2[idx];
        As[m][h] = v;
    }
    __syncthreads();
    int j = tid;
    float acc[16];
    float b = bias[j];
#pragma unroll
    for (int m = 0; m < 16; m++) acc[m] = b;
#pragma unroll 4
    for (int k = 0; k < Hh; k++) {
        float w = W[j * Hh + k];
#pragma unroll
        for (int m = 0; m < 16; m++) acc[m] += As[m][k] * w;
    }
#pragma unroll
    for (int m = 0; m < 16; m++) {
        float v = acc[m];
        if (leaky) v = v > 0.f ? v : 0.01f * v;
        Cout[(size_t)(m0 + m) * Hh + j] = v;
    }
}

// per-row top-K
__global__ void k_topk(const float* __restrict__ mat, float* __restrict__ topv,
                       int* __restrict__ topi) {
    __shared__ float vals[Nn];
    __shared__ float rv[256];
    __shared__ int ri[256];
    int row = blockIdx.x;
    int tid = threadIdx.x;
    for (int i = tid; i < Nn; i += 256) vals[i] = mat[(size_t)row * Nn + i];
    __syncthreads();
    for (int k = 0; k < Kt; k++) {
        float bv = -FLT_MAX;
        int bi = Nn;
        for (int i = tid; i < Nn; i += 256) {
            float v = vals[i];
            if (v > bv || (v == bv && i < bi)) { bv = v; bi = i; }
        }
        rv[tid] = bv; ri[tid] = bi;
        __syncthreads();
        for (int st = 128; st > 0; st >>= 1) {
            if (tid < st) {
                float ov = rv[tid + st]; int oi = ri[tid + st];
                if (ov > rv[tid] || (ov == rv[tid] && oi < ri[tid])) { rv[tid] = ov; ri[tid] = oi; }
            }
            __syncthreads();
        }
        if (tid == 0) {
            topv[row * Kt + k] = rv[0];
            topi[row * Kt + k] = ri[0];
            vals[ri[0]] = -FLT_MAX;
        }
        __syncthreads();
    }
}

// scatter: hidden_h[j] += val * h_shared[m]; colsum[j] += val
__global__ void k_scatter(const float* __restrict__ hsh, const float* __restrict__ topv,
                          const int* __restrict__ topi, float* __restrict__ hh,
                          float* __restrict__ colsum) {
    int m = blockIdx.x;
    int tid = threadIdx.x;
    float hv = hsh[(size_t)m * Hh + tid];
#pragma unroll
    for (int k = 0; k < Kt; k++) {
        int j = topi[m * Kt + k];
        float val = topv[m * Kt + k];
        atomicAdd(&hh[(size_t)j * Hh + tid], val * hv);
        if (tid == 0) atomicAdd(&colsum[j], val);
    }
}

// diag-add + v2/norm for hidden_h
__global__ void k_posthh(const float* __restrict__ hsh, const float* __restrict__ colsum,
                         const float* __restrict__ diag, float* __restrict__ hh,
                         float* __restrict__ v2, float* __restrict__ nhh) {
    __shared__ float rs[128], rq[128];
    int n = blockIdx.x;
    int tid = threadIdx.x;
    size_t idx = (size_t)n * Hh + tid;
    float v = hh[idx];
    if (colsum[n] != 0.f) {
        v += diag[n] * hsh[idx];
        hh[idx] = v;
    }
    rs[tid] = v;
    rq[tid] = v * v;
    __syncthreads();
    for (int st = 64; st > 0; st >>= 1) {
        if (tid < st) { rs[tid] += rs[tid + st]; rq[tid] += rq[tid + st]; }
        __syncthreads();
    }
    if (tid == 0) {
        v2[n] = (rs[0] != 0.f) ? 1.f : 0.f;
        nhh[n] = sqrtf(rq[0]);
    }
}

// final head
__global__ void k_final(const float* __restrict__ a, const float* __restrict__ b,
                        const float* __restrict__ c, const float* __restrict__ w,
                        const float* __restrict__ bo, float* __restrict__ out) {
    __shared__ float red[128];
    int n = blockIdx.x;
    int tid = threadIdx.x;
    size_t idx = (size_t)n * Hh + tid;
    red[tid] = (a[idx] + b[idx] + c[idx]) * w[tid];
    __syncthreads();
    for (int st = 64; st > 0; st >>= 1) {
        if (tid < st) red[tid] += red[tid + st];
        __syncthreads();
    }
    if (tid == 0) out[n] = red[0] + bo[0];
}

// ---------------------------------------------------------------------------
extern "C" void kernel_launch(void* const* d_in, const int* in_sizes, int n_in,
                              void* d_out, int out_size) {
    const float* x = (const float*)d_in[0];
    const float* cm = (const float*)d_in[1];
    const float* mv = (const float*)d_in[2];
    const float* wih0 = (const float*)d_in[3];
    const float* whh0 = (const float*)d_in[4];
    const float* bih0 = (const float*)d_in[5];
    const float* bhh0 = (const float*)d_in[6];
    const float* wih1 = (const float*)d_in[7];
    const float* whh1 = (const float*)d_in[8];
    const float* bih1 = (const float*)d_in[9];
    const float* bhh1 = (const float*)d_in[10];
    const float* w_ps = (const float*)d_in[11];
    const float* b_ps = (const float*)d_in[12];
    const float* w_hs = (const float*)d_in[13];
    const float* b_hs = (const float*)d_in[14];
    const float* w_ps_fore = (const float*)d_in[15];
    const float* b_ps_fore = (const float*)d_in[16];
    const float* w_hs_fore = (const float*)d_in[17];
    const float* b_hs_fore = (const float*)d_in[18];
    const float* w_ps_back = (const float*)d_in[19];
    const float* b_ps_back = (const float*)d_in[20];
    const float* w_hs_back = (const float*)d_in[21];
    const float* b_hs_back = (const float*)d_in[22];
    const float* w_indi = (const float*)d_in[23];
    const float* b_indi = (const float*)d_in[24];
    const float* w_out = (const float*)d_in[25];
    const float* b_out = (const float*)d_in[26];
    float* out = (float*)d_out;

    float* S;
    cudaGetSymbolAddress((void**)&S, g_buf);
    int* topi;
    cudaGetSymbolAddress((void**)&topi, g_topi);

    float* gx = S + OFF_GX;
    float* out0 = S + OFF_OUT0;
    float* xh = S + OFF_HA;
    float* wt0 = S + OFF_WT0;
    float* wt1 = S + OFF_WT1;
    float* wih1t = S + OFF_WIH1T;
    float* den = S + OFF_DEN;
    float* hidden = S + OFF_HIDDEN;
    float* v1 = S + OFF_V1;
    float* logits = S + OFF_LOGITS;
    float* cmax = S + OFF_CMAX;
    float* csum = S + OFF_CSUM;
    float* hidden2 = S + OFF_HIDDEN2;
    float* ny = S + OFF_NY;
    float* nx = S + OFF_NX;
    float* c2s = S + OFF_C2S;
    float* praw = S + OFF_PRAW;
    float* psh = S + OFF_PSH;
    float* pback = S + OFF_PBACK;
    float* outps = S + OFF_OUTPS;
    float* hsh = S + OFF_HSH;
    float* nhs = S + OFF_NHS;
    float* diag = S + OFF_DIAG;
    float* big = S + OFF_BIG;
    float* topv = S + OFF_TOPV;
    float* hh = S + OFF_HH;
    float* colsum = S + OFF_COLSUM;
    float* v2 = S + OFF_V2;
    float* nhh = S + OFF_NHH;
    float* hsiraw = S + OFF_HSIRAW;
    float* hsi = S + OFF_HSI;
    float* hback = S + OFF_HBACK;
    float* ouths = S + OFF_OUTHS;
    float* outind = S + OFF_OUTIN;
    float* xt = S + OFF_XT;
    float* wih0t = S + OFF_WIH0T;

    static bool attr_done = false;
    if (!attr_done) {
        cudaFuncSetAttribute(k_gru_layer<true>, cudaFuncAttributeMaxDynamicSharedMemorySize, SMEM_L);
        cudaFuncSetAttribute(k_gru_layer<false>, cudaFuncAttributeMaxDynamicSharedMemorySize, SMEM_L);
        attr_done = true;
    }

    // zero accumulators
    k_zero<<<(Cc + 255) / 256, 256>>>(den, Cc);
    k_zero<<<((int)SZ_NH + 255) / 256, 256>>>(hh, (int)SZ_NH);
    k_zero<<<(Nn + 255) / 256, 256>>>(colsum, Nn);

    // weight transposes + x transpose
    k_prep<<<(G * Hh + 255) / 256, 256>>>(whh0, whh1, wih1, wt0, wt1, wih1t);
    k_prep0<<<(G * Dd + 255) / 256, 256>>>(wih0, wih0t);
    k_xt<<<(Nn * Dd * Tt + 255) / 256, 256>>>(x, xt);

    // GRU: persistent layer kernels (FFMA2 packed)
    k_gru_layer<true><<<128, 512, SMEM_L>>>(xt, wih0t, bih0, wt0, bhh0, out0, nullptr);
    k_gemm_g3<<<(Tt * Nn) / 32, 256>>>(out0, wih1t, bih1, gx);
    k_gru_layer<false><<<128, 512, SMEM_L>>>(gx, nullptr, nullptr, wt1, bhh1, nullptr, xh);

    // predefined-concept branch
    k_den<<<dim3(Cc / 128, 8), 128>>>(cm, mv, den);
    k_cagg<<<Cc / 8, 256>>>(cm, mv, den, nullptr, nullptr, nullptr, xh, hidden, v1, 0);
    k_gemm_nt<<<dim3(Cc / 64, Nn / 64), 256>>>(xh, hidden, nullptr, nullptr, logits, Cc, 0);
    k_colreduce<<<Cc, 256>>>(logits, cmax, csum);
    k_cagg<<<Cc / 8, 256>>>(cm, mv, den, logits, cmax, csum, xh, hidden2, ny, 1);
    k_subnorm<<<Nn, 128>>>(xh, nullptr, xh, nx, nullptr);
    k_gemm_nt<<<dim3(Cc / 64, Nn / 64), 256>>>(xh, hidden2, nx, ny, c2s, Cc, 1);
    k_rowsoftmax<<<Nn, 256>>>(c2s, v1, Cc);
    k_gemm_nn<<<Nn / 16, 256>>>(c2s, hidden2, praw, Cc);
    k_dense<<<Nn / 16, 128>>>(praw, nullptr, nullptr, w_ps, b_ps, psh, 0);
    k_dense<<<Nn / 16, 128>>>(psh, nullptr, nullptr, w_ps_back, b_ps_back, pback, 0);
    k_dense<<<Nn / 16, 128>>>(psh, nullptr, nullptr, w_ps_fore, b_ps_fore, outps, 1);

    // hidden-concept branch
    k_subnorm<<<Nn, 128>>>(xh, pback, hsh, nhs, diag);
    k_gemm_nt<<<dim3(Nn / 64, Nn / 64), 256>>>(hsh, hsh, nhs, nhs, big, Nn, 3);
    k_topk<<<Nn, 256>>>(big, topv, topi);
    k_scatter<<<Nn, 128>>>(hsh, topv, topi, hh, colsum);
    k_posthh<<<Nn, 128>>>(hsh, colsum, diag, hh, v2, nhh);
    k_gemm_nt<<<dim3(Nn / 64, Nn / 64), 256>>>(hsh, hh, nhs, nhh, big, Nn, 1);
    k_rowsoftmax<<<Nn, 256>>>(big, v2, Nn);
    k_gemm_nn<<<Nn / 16, 256>>>(big, hh, hsiraw, Nn);
    k_dense<<<Nn / 16, 128>>>(hsiraw, nullptr, nullptr, w_hs, b_hs, hsi, 0);
    k_dense<<<Nn / 16, 128>>>(hsi, nullptr, nullptr, w_hs_back, b_hs_back, hback, 0);
    k_dense<<<Nn / 16, 128>>>(hsi, nullptr, nullptr, w_hs_fore, b_hs_fore, ouths, 1);

    // individual branch + head
    k_dense<<<Nn / 16, 128>>>(xh, pback, hback, w_indi, b_indi, outind, 1);
    k_final<<<Nn, 128>>>(outps, ouths, outind, w_out, b_out, out);
}

// round 5
// speedup vs baseline: 1.4380x; 1.4380x over previous
#include <cuda_runtime.h>
#include <cuda_bf16.h>
#include <math.h>
#include <float.h>
#include <stdint.h>

namespace {
constexpr int Nn = 4096, Cc = 512, Hh = 128, Tt = 64, Dd = 20, Kt = 10, G = 384;
constexpr int RB = 28;          // rows per GRU block
constexpr int GRU_GRID = 147;   // 147*28 = 4116 >= 4096

constexpr size_t SZ_GX = (size_t)Tt * Nn * G;
constexpr size_t SZ_OUT0 = (size_t)Tt * Nn * Hh;
constexpr size_t SZ_NH = (size_t)Nn * Hh;
constexpr size_t SZ_WT = (size_t)Hh * G;
constexpr size_t SZ_CH = (size_t)Cc * Hh;
constexpr size_t SZ_NC = (size_t)Nn * Cc;
constexpr size_t SZ_BIG = (size_t)Nn * Nn;

constexpr size_t OFF_GX = 0;
constexpr size_t OFF_OUT0 = OFF_GX + SZ_GX;
constexpr size_t OFF_HA = OFF_OUT0 + SZ_OUT0;
constexpr size_t OFF_HB = OFF_HA + SZ_NH;
constexpr size_t OFF_WT0 = OFF_HB + SZ_NH;
constexpr size_t OFF_WT1 = OFF_WT0 + SZ_WT;
constexpr size_t OFF_WIH1T = OFF_WT1 + SZ_WT;
constexpr size_t OFF_DEN = OFF_WIH1T + SZ_WT;
constexpr size_t OFF_HIDDEN = OFF_DEN + Cc;
constexpr size_t OFF_V1 = OFF_HIDDEN + SZ_CH;
constexpr size_t OFF_LOGITS = OFF_V1 + Cc;
constexpr size_t OFF_CMAX = OFF_LOGITS + SZ_NC;
constexpr size_t OFF_CSUM = OFF_CMAX + Cc;
constexpr size_t OFF_HIDDEN2 = OFF_CSUM + Cc;
constexpr size_t OFF_NY = OFF_HIDDEN2 + SZ_CH;
constexpr size_t OFF_NX = OFF_NY + Cc;
constexpr size_t OFF_C2S = OFF_NX + Nn;
constexpr size_t OFF_PRAW = OFF_C2S + SZ_NC;
constexpr size_t OFF_PSH = OFF_PRAW + SZ_NH;
constexpr size_t OFF_PBACK = OFF_PSH + SZ_NH;
constexpr size_t OFF_OUTPS = OFF_PBACK + SZ_NH;
constexpr size_t OFF_HSH = OFF_OUTPS + SZ_NH;
constexpr size_t OFF_NHS = OFF_HSH + SZ_NH;
constexpr size_t OFF_DIAG = OFF_NHS + Nn;
constexpr size_t OFF_BIG = OFF_DIAG + Nn;
constexpr size_t OFF_TOPV = OFF_BIG + SZ_BIG;
constexpr size_t OFF_HH = OFF_TOPV + (size_t)Nn * Kt;
constexpr size_t OFF_COLSUM = OFF_HH + SZ_NH;
constexpr size_t OFF_V2 = OFF_COLSUM + Nn;
constexpr size_t OFF_NHH = OFF_V2 + Nn;
constexpr size_t OFF_HSIRAW = OFF_NHH + Nn;
constexpr size_t OFF_HSI = OFF_HSIRAW + SZ_NH;
constexpr size_t OFF_HBACK = OFF_HSI + SZ_NH;
constexpr size_t OFF_OUTHS = OFF_HBACK + SZ_NH;
constexpr size_t OFF_OUTIN = OFF_OUTHS + SZ_NH;
constexpr size_t OFF_XT = OFF_OUTIN + SZ_NH;
constexpr size_t OFF_WIH0T = OFF_XT + (size_t)Tt * Nn * Dd;
constexpr size_t TOTAL = OFF_WIH0T + (size_t)Dd * G;

constexpr int SMEM_L = (128 * G + RB * Hh + RB * Dd) * 4;  // 213184 bytes
}  // namespace

__device__ float g_buf[TOTAL];
__device__ int g_topi[Nn * Kt];

__device__ __forceinline__ float fsig(float x) {
    return __fdividef(1.f, 1.f + __expf(-x));
}
__device__ __forceinline__ float ftanh(float x) {
    float y;
    asm("tanh.approx.f32 %0, %1;" : "=f"(y) : "f"(x));
    return y;
}

// ---------------------------------------------------------------------------
// prep kernels (ordered so launch #6 is k_gru_layer<true> for ncu -s 5 -c 1)
// ---------------------------------------------------------------------------
__global__ void k_zero(float* p, int n) {
    int i = blockIdx.x * blockDim.x + threadIdx.x;
    if (i < n) p[i] = 0.f;
}
__global__ void k_zero2(float* p1, int n1, float* p2, int n2) {
    int i = blockIdx.x * blockDim.x + threadIdx.x;
    if (i < n1) p1[i] = 0.f;
    if (i < n2) p2[i] = 0.f;
}

// transpose [G,H] -> [H,G] for whh0, whh1, wih1
__global__ void k_prep(const float* __restrict__ w0, const float* __restrict__ w1,
                       const float* __restrict__ w2, float* __restrict__ t0,
                       float* __restrict__ t1, float* __restrict__ t2) {
    int i = blockIdx.x * blockDim.x + threadIdx.x;
    if (i >= G * Hh) return;
    int r = i / Hh, c = i % Hh;
    t0[c * G + r] = w0[i];
    t1[c * G + r] = w1[i];
    t2[c * G + r] = w2[i];
}

// wih0 [G,D] -> [D,G]
__global__ void k_prep0(const float* __restrict__ w, float* __restrict__ t) {
    int i = blockIdx.x * blockDim.x + threadIdx.x;
    if (i >= G * Dd) return;
    int r = i / Dd, c = i % Dd;
    t[c * G + r] = w[i];
}

// x [N, D*T] -> xt [T, N, D]
__global__ void k_xt(const float* __restrict__ x, float* __restrict__ xt) {
    int i = blockIdx.x * blockDim.x + threadIdx.x;
    if (i >= Nn * Dd * Tt) return;
    int t = i % Tt;
    int d = (i / Tt) % Dd;
    int n = i / (Tt * Dd);
    xt[((size_t)t * Nn + n) * Dd + d] = x[i];
}

// ---------------------------------------------------------------------------
// Persistent GRU layer: grid=147 (all SMs), 512 threads, 28 rows/block.
// whhT (192KB) cached in smem; h lives in smem across all 64 steps.
// Thread j owns gate columns j, j+128, j+256 -> register-local epilogue.
// ---------------------------------------------------------------------------
template <bool L0>
__global__ __launch_bounds__(512, 1) void k_gru_layer(
    const float* __restrict__ xin,  // L0: xt [T,N,D]; L1: gx [T,N,G]
    const float* __restrict__ wih0t, const float* __restrict__ bih0,
    const float* __restrict__ wt, const float* __restrict__ bhh,
    float* __restrict__ out0, float* __restrict__ xh) {
    extern __shared__ float sm[];
    float* ws = sm;                 // [128][384]
    float* hs = sm + 128 * G;       // [28][128]
    float* xs = hs + RB * Hh;       // [28][20]
    int tid = threadIdx.x;
    int j = tid & 127, rg = tid >> 7;  // rg 0..3
    int n0 = blockIdx.x * RB;
    int r0 = rg * 7;  // 7 rows per thread group

    {
        const float4* s = (const float4*)wt;
        float4* d = (float4*)ws;
        for (int e = tid; e < 128 * G / 4; e += 512) d[e] = s[e];
    }
    for (int e = tid; e < RB * Hh; e += 512) hs[e] = 0.f;

    float br = bhh[j], bz = bhh[j + 128], bn = bhh[j + 256];
    float bir = 0.f, biz = 0.f, bin = 0.f;
    if (L0) { bir = bih0[j]; biz = bih0[j + 128]; bin = bih0[j + 256]; }

    for (int t = 0; t < Tt; t++) {
        if (L0) {
            const float* src = xin + ((size_t)t * Nn + n0) * Dd;
            for (int e = tid; e < RB * Dd; e += 512)
                xs[e] = (n0 + e / Dd < Nn) ? src[e] : 0.f;
        }
        __syncthreads();
        float ar[7], az[7], axn[7], ahn[7];
        if (L0) {
#pragma unroll
            for (int m = 0; m < 7; m++) {
                ar[m] = br + bir; az[m] = bz + biz; axn[m] = bin; ahn[m] = bn;
            }
#pragma unroll 4
            for (int d = 0; d < Dd; d++) {
                float wr = wih0t[d * G + j];
                float wz = wih0t[d * G + j + 128];
                float wn = wih0t[d * G + j + 256];
#pragma unroll
                for (int m = 0; m < 7; m++) {
                    float xv = xs[(r0 + m) * Dd + d];
                    ar[m] += xv * wr; az[m] += xv * wz; axn[m] += xv * wn;
                }
            }
        } else {
            const float* gp = xin + ((size_t)t * Nn + n0) * G;
#pragma unroll
            for (int m = 0; m < 7; m++) {
                bool ok = (n0 + r0 + m) < Nn;
                ar[m] = ok ? gp[(r0 + m) * G + j] + br : 0.f;
                az[m] = ok ? gp[(r0 + m) * G + j + 128] + bz : 0.f;
                axn[m] = ok ? gp[(r0 + m) * G + j + 256] : 0.f;
                ahn[m] = bn;
            }
        }
        // recurrent GEMM: gh += h_prev @ whhT
        for (int k = 0; k < Hh; k += 4) {
            float4 hv[7];
#pragma unroll
            for (int m = 0; m < 7; m++)
                hv[m] = *(const float4*)&hs[(r0 + m) * Hh + k];
#pragma unroll
            for (int kk = 0; kk < 4; kk++) {
                float wr = ws[(k + kk) * G + j];
                float wz = ws[(k + kk) * G + j + 128];
                float wn = ws[(k + kk) * G + j + 256];
#pragma unroll
                for (int m = 0; m < 7; m++) {
                    float h = (kk == 0) ? hv[m].x : (kk == 1) ? hv[m].y
                              : (kk == 2) ? hv[m].z : hv[m].w;
                    ar[m] += h * wr; az[m] += h * wz; ahn[m] += h * wn;
                }
            }
        }
        float hnew[7];
#pragma unroll
        for (int m = 0; m < 7; m++) {
            float r = fsig(ar[m]);
            float z = fsig(az[m]);
            float nc = ftanh(axn[m] + r * ahn[m]);
            float hold = hs[(r0 + m) * Hh + j];
            hnew[m] = (1.f - z) * nc + z * hold;
        }
        __syncthreads();  // all hs reads done
#pragma unroll
        for (int m = 0; m < 7; m++) {
            int n = n0 + r0 + m;
            hs[(r0 + m) * Hh + j] = hnew[m];
            if (n < Nn) {
                if (L0)
                    out0[((size_t)t * Nn + n) * Hh + j] = hnew[m];
                else if (t == Tt - 1)
                    xh[(size_t)n * Hh + j] = hnew[m];
            }
        }
    }
}

// ---------------------------------------------------------------------------
// gx1 = out0 @ wih1T + bih1   (M = T*N, 3-col-per-thread layout, TM=32)
// ---------------------------------------------------------------------------
__global__ __launch_bounds__(256, 2) void k_gemm_g3(
    const float* __restrict__ A, const float* __restrict__ WT,
    const float* __restrict__ bias, float* __restrict__ Cout) {
    __shared__ float As[32 * Hh];
    int tid = threadIdx.x;
    int j = tid & 127, rg = tid >> 7;  // rg 0..1, 16 rows each
    int m0 = blockIdx.x * 32;
    {
        const float4* s = (const float4*)(A + (size_t)m0 * Hh);
        float4* d = (float4*)As;
        for (int e = tid; e < 32 * Hh / 4; e += 256) d[e] = s[e];
    }
    __syncthreads();
    int r0 = rg * 16;
    float ar[16], az[16], an[16];
#pragma unroll
    for (int m = 0; m < 16; m++) { ar[m] = 0.f; az[m] = 0.f; an[m] = 0.f; }
    for (int k = 0; k < Hh; k += 2) {
        float2 hv[16];
#pragma unroll
        for (int m = 0; m < 16; m++)
            hv[m] = *(const float2*)&As[(r0 + m) * Hh + k];
#pragma unroll
        for (int kk = 0; kk < 2; kk++) {
            float wr = WT[(k + kk) * G + j];
            float wz = WT[(k + kk) * G + j + 128];
            float wn = WT[(k + kk) * G + j + 256];
#pragma unroll
            for (int m = 0; m < 16; m++) {
                float h = kk ? hv[m].y : hv[m].x;
                ar[m] += h * wr; az[m] += h * wz; an[m] += h * wn;
            }
        }
    }
    float br = bias[j], bz = bias[j + 128], bn = bias[j + 256];
#pragma unroll
    for (int m = 0; m < 16; m++) {
        size_t base = (size_t)(m0 + r0 + m) * G;
        Cout[base + j] = ar[m] + br;
        Cout[base + j + 128] = az[m] + bz;
        Cout[base + j + 256] = an[m] + bn;
    }
}

// den[c] = sum_n cm[n,c]*mv[n]
__global__ void k_den(const float* __restrict__ cm, const float* __restrict__ mv,
                      float* __restrict__ den) {
    int c = blockIdx.x * 128 + threadIdx.x;
    int nb = blockIdx.y;
    float s = 0.f;
    for (int n = nb * 512; n < (nb + 1) * 512; n++) s += cm[(size_t)n * Cc + c] * mv[n];
    atomicAdd(&den[c], s);
}

// Weighted aggregation into [C,H]: mode 0 -> hidden (+v1), mode 1 -> hidden2 (+norm)
__global__ void k_cagg(const float* __restrict__ cm, const float* __restrict__ mv,
                       const float* __restrict__ den, const float* __restrict__ logits,
                       const float* __restrict__ cmax, const float* __restrict__ csum,
                       const float* __restrict__ xh, float* __restrict__ outp,
                       float* __restrict__ aux, int mode) {
    __shared__ float xs[64][Hh];
    __shared__ float cs[64][8];
    __shared__ float red[256];
    int c0 = blockIdx.x * 8;
    int tid = threadIdx.x;
    int h = tid & 127, g = tid >> 7;
    float acc[4] = {0.f, 0.f, 0.f, 0.f};
    for (int nb = 0; nb < Nn; nb += 64) {
        for (int e = tid; e < 64 * Hh; e += 256)
            xs[e >> 7][e & 127] = xh[(size_t)(nb + (e >> 7)) * Hh + (e & 127)];
        for (int e = tid; e < 64 * 8; e += 256) {
            int nn = e >> 3, ci = e & 7;
            int n = nb + nn, c = c0 + ci;
            float coef;
            if (mode == 0) {
                float cv = cm[(size_t)n * Cc + c];
                coef = cv * mv[n] / (den[c] * cv + 1.f);
            } else {
                coef = __expf(logits[(size_t)n * Cc + c] - cmax[c]) / csum[c];
            }
            cs[nn][ci] = coef;
        }
        __syncthreads();
#pragma unroll 4
        for (int nn = 0; nn < 64; nn++) {
            float xv = xs[nn][h];
#pragma unroll
            for (int u = 0; u < 4; u++) acc[u] += cs[nn][g + 2 * u] * xv;
        }
        __syncthreads();
    }
#pragma unroll
    for (int u = 0; u < 4; u++) outp[(size_t)(c0 + g + 2 * u) * Hh + h] = acc[u];
    for (int u = 0; u < 4; u++) {
        red[tid] = (mode == 0) ? acc[u] : acc[u] * acc[u];
        __syncthreads();
        for (int st = 64; st > 0; st >>= 1) {
            if (h < st) red[tid] += red[tid + st];
            __syncthreads();
        }
        if (h == 0) {
            int c = c0 + g + 2 * u;
            aux[c] = (mode == 0) ? ((red[tid] != 0.f) ? 1.f : 0.f) : sqrtf(red[tid]);
        }
        __syncthreads();
    }
}

// Out = A [- B]; nrm = ||row||; diag = ss/max(ss,1e-12)
__global__ void k_subnorm(const float* __restrict__ A, const float* __restrict__ B,
                          float* __restrict__ Out, float* __restrict__ nrm,
                          float* __restrict__ diag) {
    __shared__ float red[128];
    int n = blockIdx.x;
    int tid = threadIdx.x;
    float v = A[(size_t)n * Hh + tid];
    if (B) v -= B[(size_t)n * Hh + tid];
    Out[(size_t)n * Hh + tid] = v;
    red[tid] = v * v;
    __syncthreads();
    for (int st = 64; st > 0; st >>= 1) {
        if (tid < st) red[tid] += red[tid + st];
        __syncthreads();
    }
    if (tid == 0) {
        float ss = red[0];
        nrm[n] = sqrtf(ss);
        if (diag) diag[n] = ss / fmaxf(ss, 1e-12f);
    }
}

// NT GEMM, K=128; flags: 1=cosine-normalize, 2=zero diag
__global__ void k_gemm_nt(const float* __restrict__ A, const float* __restrict__ B,
                          const float* __restrict__ nx, const float* __restrict__ ny,
                          float* __restrict__ Cmat, int Ndim, int flags) {
    __shared__ float As[64][33];
    __shared__ float Bs[64][33];
    int m0 = blockIdx.y * 64, n0 = blockIdx.x * 64;
    int tid = threadIdx.x;
    int ty = tid / 16, tx = tid % 16;
    float acc[4][4];
#pragma unroll
    for (int i = 0; i < 4; i++)
#pragma unroll
        for (int jj = 0; jj < 4; jj++) acc[i][jj] = 0.f;
    for (int kc = 0; kc < Hh; kc += 32) {
        for (int e = tid; e < 64 * 32; e += 256) {
            int r = e / 32, c = e % 32;
            As[r][c] = A[(size_t)(m0 + r) * Hh + kc + c];
            Bs[r][c] = B[(size_t)(n0 + r) * Hh + kc + c];
        }
        __syncthreads();
#pragma unroll 8
        for (int kk = 0; kk < 32; kk++) {
            float a[4], b[4];
#pragma unroll
            for (int i = 0; i < 4; i++) a[i] = As[ty * 4 + i][kk];
#pragma unroll
            for (int jj = 0; jj < 4; jj++) b[jj] = Bs[tx * 4 + jj][kk];
#pragma unroll
            for (int i = 0; i < 4; i++)
#pragma unroll
                for (int jj = 0; jj < 4; jj++) acc[i][jj] += a[i] * b[jj];
        }
        __syncthreads();
    }
#pragma unroll
    for (int i = 0; i < 4; i++) {
        int gm = m0 + ty * 4 + i;
#pragma unroll
        for (int jj = 0; jj < 4; jj++) {
            int gn = n0 + tx * 4 + jj;
            float v = acc[i][jj];
            if (flags & 1) v = v / fmaxf(nx[gm] * ny[gn], 1e-12f);
            if ((flags & 2) && gm == gn) v = 0.f;
            Cmat[(size_t)gm * Ndim + gn] = v;
        }
    }
}

// column reduce over logits [N,C]
__global__ void k_colreduce(const float* __restrict__ logits, float* __restrict__ cmax,
                            float* __restrict__ csum) {
    __shared__ float col[Nn];
    __shared__ float red[256];
    int c = blockIdx.x;
    int tid = threadIdx.x;
    for (int n = tid; n < Nn; n += 256) col[n] = logits[(size_t)n * Cc + c];
    __syncthreads();
    float m = -FLT_MAX;
    for (int n = tid; n < Nn; n += 256) m = fmaxf(m, col[n]);
    red[tid] = m;
    __syncthreads();
    for (int st = 128; st > 0; st >>= 1) {
        if (tid < st) red[tid] = fmaxf(red[tid], red[tid + st]);
        __syncthreads();
    }
    float mx = red[0];
    __syncthreads();
    float s = 0.f;
    for (int n = tid; n < Nn; n += 256) s += __expf(col[n] - mx);
    red[tid] = s;
    __syncthreads();
    for (int st = 128; st > 0; st >>= 1) {
        if (tid < st) red[tid] += red[tid + st];
        __syncthreads();
    }
    if (tid == 0) { cmax[c] = mx; csum[c] = red[0]; }
}

// row softmax with validity mask, in place
__global__ void k_rowsoftmax(float* __restrict__ mat, const float* __restrict__ v, int W) {
    __shared__ float buf[Nn];
    __shared__ float red[256];
    int row = blockIdx.x;
    int tid = threadIdx.x;
    float* r = mat + (size_t)row * W;
    for (int i = tid; i < W; i += 256) buf[i] = (v[i] != 0.f) ? r[i] : -1e9f;
    __syncthreads();
    float m = -FLT_MAX;
    for (int i = tid; i < W; i += 256) m = fmaxf(m, buf[i]);
    red[tid] = m;
    __syncthreads();
    for (int st = 128; st > 0; st >>= 1) {
        if (tid < st) red[tid] = fmaxf(red[tid], red[tid + st]);
        __syncthreads();
    }
    float mx = red[0];
    __syncthreads();
    float s = 0.f;
    for (int i = tid; i < W; i += 256) s += __expf(buf[i] - mx);
    red[tid] = s;
    __syncthreads();
    for (int st = 128; st > 0; st >>= 1) {
        if (tid < st) red[tid] += red[tid + st];
        __syncthreads();
    }
    float inv = 1.f / red[0];
    for (int i = tid; i < W; i += 256)
        r[i] = (v[i] != 0.f) ? __expf(buf[i] - mx) * inv : 0.f;
}

// NN GEMM: C[M,128] = A[M,K] @ B[K,128]; BM=32, BK=32, 4x4 register tile
__global__ __launch_bounds__(256, 4) void k_gemm_nn(
    const float* __restrict__ A, const float* __restrict__ B,
    float* __restrict__ Cout, int K) {
    __shared__ float As[32][33];
    __shared__ float Bs[32][128];
    int m0 = blockIdx.x * 32;
    int tid = threadIdx.x;
    int ty = tid >> 5;   // 0..7: row group (4 rows)
    int tx = tid & 31;   // 0..31: col group (4 cols)
    float acc[4][4];
#pragma unroll
    for (int i = 0; i < 4; i++)
#pragma unroll
        for (int jj = 0; jj < 4; jj++) acc[i][jj] = 0.f;
    for (int ck = 0; ck < K; ck += 32) {
        for (int e = tid; e < 32 * 32; e += 256)
            As[e >> 5][e & 31] = A[(size_t)(m0 + (e >> 5)) * K + ck + (e & 31)];
        for (int e = tid; e < 32 * 128; e += 256)
            Bs[e >> 7][e & 127] = B[(size_t)(ck + (e >> 7)) * Hh + (e & 127)];
        __syncthreads();
#pragma unroll 8
        for (int kk = 0; kk < 32; kk++) {
            float4 b4 = *(const float4*)&Bs[kk][tx * 4];
            float a[4];
#pragma unroll
            for (int i = 0; i < 4; i++) a[i] = As[ty * 4 + i][kk];
#pragma unroll
            for (int i = 0; i < 4; i++) {
                acc[i][0] += a[i] * b4.x;
                acc[i][1] += a[i] * b4.y;
                acc[i][2] += a[i] * b4.z;
                acc[i][3] += a[i] * b4.w;
            }
        }
        __syncthreads();
    }
#pragma unroll
    for (int i = 0; i < 4; i++) {
        float4 v = make_float4(acc[i][0], acc[i][1], acc[i][2], acc[i][3]);
        *(float4*)&Cout[(size_t)(m0 + ty * 4 + i) * Hh + tx * 4] = v;
    }
}

// Dense H->H: C = (A0 [-A1] [-A2]) @ W^T + bias, optional leaky relu
__global__ void k_dense(const float* __restrict__ A0, const float* __restrict__ A1,
                        const float* __restrict__ A2, const float* __restrict__ W,
                        const float* __restrict__ bias, float* __restrict__ Cout, int leaky) {
    __shared__ float As[16][Hh];
    int m0 = blockIdx.x * 16;
    int tid = threadIdx.x;
    for (int e = tid; e < 16 * Hh; e += 128) {
        int m = e >> 7, h = e & 127;
        size_t idx = (size_t)(m0 + m) * Hh + h;
        float v = A0[idx];
        if (A1) v -= A1[idx];
        if (A2) v -= A2[idx];
        As[m][h] = v;
    }
    __syncthreads();
    int j = tid;
    float acc[16];
    float b = bias[j];
#pragma unroll
    for (int m = 0; m < 16; m++) acc[m] = b;
#pragma unroll 4
    for (int k = 0; k < Hh; k++) {
        float w = W[j * Hh + k];
#pragma unroll
        for (int m = 0; m < 16; m++) acc[m] += As[m][k] * w;
    }
#pragma unroll
    for (int m = 0; m < 16; m++) {
        float v = acc[m];
        if (leaky) v = v > 0.f ? v : 0.01f * v;
        Cout[(size_t)(m0 + m) * Hh + j] = v;
    }
}

// per-row top-K
__global__ void k_topk(const float* __restrict__ mat, float* __restrict__ topv,
                       int* __restrict__ topi) {
    __shared__ float vals[Nn];
    __shared__ float rv[256];
    __shared__ int ri[256];
    int row = blockIdx.x;
    int tid = threadIdx.x;
    for (int i = tid; i < Nn; i += 256) vals[i] = mat[(size_t)row * Nn + i];
    __syncthreads();
    for (int k = 0; k < Kt; k++) {
        float bv = -FLT_MAX;
        int bi = Nn;
        for (int i = tid; i < Nn; i += 256) {
            float v = vals[i];
            if (v > bv || (v == bv && i < bi)) { bv = v; bi = i; }
        }
        rv[tid] = bv; ri[tid] = bi;
        __syncthreads();
        for (int st = 128; st > 0; st >>= 1) {
            if (tid < st) {
                float ov = rv[tid + st]; int oi = ri[tid + st];
                if (ov > rv[tid] || (ov == rv[tid] && oi < ri[tid])) { rv[tid] = ov; ri[tid] = oi; }
            }
            __syncthreads();
        }
        if (tid == 0) {
            topv[row * Kt + k] = rv[0];
            topi[row * Kt + k] = ri[0];
            vals[ri[0]] = -FLT_MAX;
        }
        __syncthreads();
    }
}

// scatter: hidden_h[j] += val * h_shared[m]; colsum[j] += val
__global__ void k_scatter(const float* __restrict__ hsh, const float* __restrict__ topv,
                          const int* __restrict__ topi, float* __restrict__ hh,
                          float* __restrict__ colsum) {
    int m = blockIdx.x;
    int tid = threadIdx.x;
    float hv = hsh[(size_t)m * Hh + tid];
#pragma unroll
    for (int k = 0; k < Kt; k++) {
        int j = topi[m * Kt + k];
        float val = topv[m * Kt + k];
        atomicAdd(&hh[(size_t)j * Hh + tid], val * hv);
        if (tid == 0) atomicAdd(&colsum[j], val);
    }
}

// diag-add + v2/norm for hidden_h
__global__ void k_posthh(const float* __restrict__ hsh, const float* __restrict__ colsum,
                         const float* __restrict__ diag, float* __restrict__ hh,
                         float* __restrict__ v2, float* __restrict__ nhh) {
    __shared__ float rs[128], rq[128];
    int n = blockIdx.x;
    int tid = threadIdx.x;
    size_t idx = (size_t)n * Hh + tid;
    float v = hh[idx];
    if (colsum[n] != 0.f) {
        v += diag[n] * hsh[idx];
        hh[idx] = v;
    }
    rs[tid] = v;
    rq[tid] = v * v;
    __syncthreads();
    for (int st = 64; st > 0; st >>= 1) {
        if (tid < st) { rs[tid] += rs[tid + st]; rq[tid] += rq[tid + st]; }
        __syncthreads();
    }
    if (tid == 0) {
        v2[n] = (rs[0] != 0.f) ? 1.f : 0.f;
        nhh[n] = sqrtf(rq[0]);
    }
}

// final head
__global__ void k_final(const float* __restrict__ a, const float* __restrict__ b,
                        const float* __restrict__ c, const float* __restrict__ w,
                        const float* __restrict__ bo, float* __restrict__ out) {
    __shared__ float red[128];
    int n = blockIdx.x;
    int tid = threadIdx.x;
    size_t idx = (size_t)n * Hh + tid;
    red[tid] = (a[idx] + b[idx] + c[idx]) * w[tid];
    __syncthreads();
    for (int st = 64; st > 0; st >>= 1) {
        if (tid < st) red[tid] += red[tid + st];
        __syncthreads();
    }
    if (tid == 0) out[n] = red[0] + bo[0];
}

// ---------------------------------------------------------------------------
extern "C" void kernel_launch(void* const* d_in, const int* in_sizes, int n_in,
                              void* d_out, int out_size) {
    const float* x = (const float*)d_in[0];
    const float* cm = (const float*)d_in[1];
    const float* mv = (const float*)d_in[2];
    const float* wih0 = (const float*)d_in[3];
    const float* whh0 = (const float*)d_in[4];
    const float* bih0 = (const float*)d_in[5];
    const float* bhh0 = (const float*)d_in[6];
    const float* wih1 = (const float*)d_in[7];
    const float* whh1 = (const float*)d_in[8];
    const float* bih1 = (const float*)d_in[9];
    const float* bhh1 = (const float*)d_in[10];
    const float* w_ps = (const float*)d_in[11];
    const float* b_ps = (const float*)d_in[12];
    const float* w_hs = (const float*)d_in[13];
    const float* b_hs = (const float*)d_in[14];
    const float* w_ps_fore = (const float*)d_in[15];
    const float* b_ps_fore = (const float*)d_in[16];
    const float* w_hs_fore = (const float*)d_in[17];
    const float* b_hs_fore = (const float*)d_in[18];
    const float* w_ps_back = (const float*)d_in[19];
    const float* b_ps_back = (const float*)d_in[20];
    const float* w_hs_back = (const float*)d_in[21];
    const float* b_hs_back = (const float*)d_in[22];
    const float* w_indi = (const float*)d_in[23];
    const float* b_indi = (const float*)d_in[24];
    const float* w_out = (const float*)d_in[25];
    const float* b_out = (const float*)d_in[26];
    float* out = (float*)d_out;

    float* S;
    cudaGetSymbolAddress((void**)&S, g_buf);
    int* topi;
    cudaGetSymbolAddress((void**)&topi, g_topi);

    float* gx = S + OFF_GX;
    float* out0 = S + OFF_OUT0;
    float* xh = S + OFF_HA;
    float* wt0 = S + OFF_WT0;
    float* wt1 = S + OFF_WT1;
    float* wih1t = S + OFF_WIH1T;
    float* den = S + OFF_DEN;
    float* hidden = S + OFF_HIDDEN;
    float* v1 = S + OFF_V1;
    float* logits = S + OFF_LOGITS;
    float* cmax = S + OFF_CMAX;
    float* csum = S + OFF_CSUM;
    float* hidden2 = S + OFF_HIDDEN2;
    float* ny = S + OFF_NY;
    float* nx = S + OFF_NX;
    float* c2s = S + OFF_C2S;
    float* praw = S + OFF_PRAW;
    float* psh = S + OFF_PSH;
    float* pback = S + OFF_PBACK;
    float* outps = S + OFF_OUTPS;
    float* hsh = S + OFF_HSH;
    float* nhs = S + OFF_NHS;
    float* diag = S + OFF_DIAG;
    float* big = S + OFF_BIG;
    float* topv = S + OFF_TOPV;
    float* hh = S + OFF_HH;
    float* colsum = S + OFF_COLSUM;
    float* v2 = S + OFF_V2;
    float* nhh = S + OFF_NHH;
    float* hsiraw = S + OFF_HSIRAW;
    float* hsi = S + OFF_HSI;
    float* hback = S + OFF_HBACK;
    float* ouths = S + OFF_OUTHS;
    float* outind = S + OFF_OUTIN;
    float* xt = S + OFF_XT;
    float* wih0t = S + OFF_WIH0T;

    static bool attr_done = false;
    if (!attr_done) {
        cudaFuncSetAttribute(k_gru_layer<true>, cudaFuncAttributeMaxDynamicSharedMemorySize, SMEM_L);
        cudaFuncSetAttribute(k_gru_layer<false>, cudaFuncAttributeMaxDynamicSharedMemorySize, SMEM_L);
        attr_done = true;
    }

    // --- exactly 5 launches before L0 so ncu (-s 5 -c 1) captures the GRU ---
    k_prep<<<(G * Hh + 255) / 256, 256>>>(whh0, whh1, wih1, wt0, wt1, wih1t);   // 1
    k_prep0<<<(G * Dd + 255) / 256, 256>>>(wih0, wih0t);                        // 2
    k_xt<<<(Nn * Dd * Tt + 255) / 256, 256>>>(x, xt);                           // 3
    k_zero<<<((int)SZ_NH + 255) / 256, 256>>>(hh, (int)SZ_NH);                  // 4
    k_zero2<<<(Nn + 255) / 256, 256>>>(den, Cc, colsum, Nn);                    // 5

    // GRU: persistent layer kernels on all 148 SMs
    k_gru_layer<true><<<GRU_GRID, 512, SMEM_L>>>(xt, wih0t, bih0, wt0, bhh0, out0, nullptr);  // 6 <- profiled
    k_gemm_g3<<<(Tt * Nn) / 32, 256>>>(out0, wih1t, bih1, gx);
    k_gru_layer<false><<<GRU_GRID, 512, SMEM_L>>>(gx, nullptr, nullptr, wt1, bhh1, nullptr, xh);

    // predefined-concept branch
    k_den<<<dim3(Cc / 128, 8), 128>>>(cm, mv, den);
    k_cagg<<<Cc / 8, 256>>>(cm, mv, den, nullptr, nullptr, nullptr, xh, hidden, v1, 0);
    k_gemm_nt<<<dim3(Cc / 64, Nn / 64), 256>>>(xh, hidden, nullptr, nullptr, logits, Cc, 0);
    k_colreduce<<<Cc, 256>>>(logits, cmax, csum);
    k_cagg<<<Cc / 8, 256>>>(cm, mv, den, logits, cmax, csum, xh, hidden2, ny, 1);
    k_subnorm<<<Nn, 128>>>(xh, nullptr, xh, nx, nullptr);
    k_gemm_nt<<<dim3(Cc / 64, Nn / 64), 256>>>(xh, hidden2, nx, ny, c2s, Cc, 1);
    k_rowsoftmax<<<Nn, 256>>>(c2s, v1, Cc);
    k_gemm_nn<<<Nn / 32, 256>>>(c2s, hidden2, praw, Cc);
    k_dense<<<Nn / 16, 128>>>(praw, nullptr, nullptr, w_ps, b_ps, psh, 0);
    k_dense<<<Nn / 16, 128>>>(psh, nullptr, nullptr, w_ps_back, b_ps_back, pback, 0);
    k_dense<<<Nn / 16, 128>>>(psh, nullptr, nullptr, w_ps_fore, b_ps_fore, outps, 1);

    // hidden-concept branch
    k_subnorm<<<Nn, 128>>>(xh, pback, hsh, nhs, diag);
    k_gemm_nt<<<dim3(Nn / 64, Nn / 64), 256>>>(hsh, hsh, nhs, nhs, big, Nn, 3);
    k_topk<<<Nn, 256>>>(big, topv, topi);
    k_scatter<<<Nn, 128>>>(hsh, topv, topi, hh, colsum);
    k_posthh<<<Nn, 128>>>(hsh, colsum, diag, hh, v2, nhh);
    k_gemm_nt<<<dim3(Nn / 64, Nn / 64), 256>>>(hsh, hh, nhs, nhh, big, Nn, 1);
    k_rowsoftmax<<<Nn, 256>>>(big, v2, Nn);
    k_gemm_nn<<<Nn / 32, 256>>>(big, hh, hsiraw, Nn);
    k_dense<<<Nn / 16, 128>>>(hsiraw, nullptr, nullptr, w_hs, b_hs, hsi, 0);
    k_dense<<<Nn / 16, 128>>>(hsi, nullptr, nullptr, w_hs_back, b_hs_back, hback, 0);
    k_dense<<<Nn / 16, 128>>>(hsi, nullptr, nullptr, w_hs_fore, b_hs_fore, ouths, 1);

    // individual branch + head
    k_dense<<<Nn / 16, 128>>>(xh, pback, hback, w_indi, b_indi, outind, 1);
    k_final<<<Nn, 128>>>(outps, ouths, outind, w_out, b_out, out);
}